// round 10
// baseline (speedup 1.0000x reference)
#include <cuda_runtime.h>
#include <cstdint>

// GraphAttention: nf=x@W ; g=head-sum(nf) ; s1/s2=g.a1/a2 ; lrelu+mask+softmax(j) ; agg.
// Pass = 64 rows (4 graphs). GEMM: lane->row, W broadcast. nf pitch 132 (quad-odd).
#define NN      16
#define FINN    64
#define COLS    128
#define ROWS_PP 64
#define NPASS   8192
#define GRID    2048
#define THREADS 256

// smem offsets (floats)
#define OFF_W   0            // [64 k][128 c]
#define OFF_NF  8192         // [64 r][132]
#define OFF_XA  16640        // x: [64 r][65] (scalar) / attn: [i*84 + h*20 + j]  (aliased)
#define OFF_S1  22016        // [64][4]
#define OFF_S2  22272
#define OFF_A1  22528        // [4][36]
#define OFF_A2  22672
#define SMEM_FLOATS 22816
#define SMEM_BYTES  (SMEM_FLOATS * 4)

typedef unsigned long long ull;

__device__ __forceinline__ ull pack2(float lo, float hi) {
    ull o; asm("mov.b64 %0, {%1, %2};" : "=l"(o) : "f"(lo), "f"(hi)); return o;
}
__device__ __forceinline__ void fma2(ull& d, ull a, ull b, ull c) {
    asm("fma.rn.f32x2 %0, %1, %2, %3;" : "=l"(d) : "l"(a), "l"(b), "l"(c));
}

__global__ __launch_bounds__(THREADS, 2)
void gat_kernel(const float* __restrict__ x,
                const float* __restrict__ W,
                const float* __restrict__ attv,
                const float* __restrict__ adj,
                float* __restrict__ out)
{
    extern __shared__ float smf[];
    const int t = threadIdx.x;
    const int warp = t >> 5;
    const int lane = t & 31;

    // ---- one-time setup ----
    #pragma unroll
    for (int q = 0; q < 8; q++)
        ((float4*)(smf + OFF_W))[t + 256 * q] = ((const float4*)W)[t + 256 * q];
    {
        const int h = t >> 6, f2 = t & 63;
        const float v = attv[t];
        if (f2 < 32) smf[OFF_A1 + h * 36 + f2] = v;
        else         smf[OFF_A2 + h * 36 + (f2 - 32)] = v;
    }
    unsigned amask = 0;
    {
        const int i = (t >> 2) & 15;
        #pragma unroll
        for (int j = 0; j < NN; j++)
            if (adj[i * NN + j] != 0.f) amask |= (1u << j);
    }

    // GEMM mapping: warp -> (rowgroup = warp>>2 [32 rows], colblock = warp&3 [32 cols]); lane -> row
    const int grow = (warp >> 2) * 32 + lane;
    const int cb   = (warp & 3) * 32;
    // agg mapping: warp -> 8 i-rows; lane -> c4 (4 cols); h = lane>>3
    const int ar0  = 8 * warp;
    const int ajb  = (warp >> 1) * 16;
    const int hh   = lane >> 3;

    __syncthreads();

    for (int tp = blockIdx.x; tp < NPASS; tp += GRID) {
        const size_t row0 = (size_t)tp * ROWS_PP;

        // ---- stage x (64x64) -> pitch-65 scalar layout ----
        {
            const float4* gx = (const float4*)(x + row0 * FINN);
            #pragma unroll
            for (int q = 0; q < 4; q++) {
                const int idx = t + 256 * q;
                const float4 v = gx[idx];
                float* p = smf + OFF_XA + (idx >> 4) * 65 + 4 * (idx & 15);
                p[0] = v.x; p[1] = v.y; p[2] = v.z; p[3] = v.w;
            }
        }
        __syncthreads();

        // ---- GEMM: thread = 1 row x 32 cols; W broadcast, x lane-varying scalar ----
        {
            const float* xr = smf + OFF_XA + grow * 65;
            const float* wb = smf + OFF_W + cb;
            ull acc[16];
            #pragma unroll
            for (int q = 0; q < 16; q++) acc[q] = 0;
            #pragma unroll 8
            for (int k = 0; k < FINN; k++) {
                const float xv = xr[k];
                const ull xx = pack2(xv, xv);
                const ulonglong2* wk = (const ulonglong2*)(wb + k * COLS);
                #pragma unroll
                for (int q = 0; q < 8; q++) {
                    const ulonglong2 wv = wk[q];
                    fma2(acc[2 * q],     xx, wv.x, acc[2 * q]);
                    fma2(acc[2 * q + 1], xx, wv.y, acc[2 * q + 1]);
                }
            }
            ulonglong2* nfr = (ulonglong2*)(smf + OFF_NF + grow * 132 + cb);
            #pragma unroll
            for (int q = 0; q < 8; q++) {
                ulonglong2 st; st.x = acc[2 * q]; st.y = acc[2 * q + 1];
                nfr[q] = st;
            }
        }
        __syncthreads();

        // ---- s1/s2: thread -> (row = t>>2, fq = t&3 -> 8 f's); shfl-reduce over fq ----
        {
            const int row = t >> 2, fq = t & 3;
            const int fb = fq * 8;
            const float* nfr = smf + OFF_NF + row * 132 + fb;
            float g[8];
            #pragma unroll
            for (int b4 = 0; b4 < 2; b4++) {
                float4 s = *(const float4*)(nfr + b4 * 4);
                const float4 n1 = *(const float4*)(nfr + 32 + b4 * 4);
                const float4 n2 = *(const float4*)(nfr + 64 + b4 * 4);
                const float4 n3 = *(const float4*)(nfr + 96 + b4 * 4);
                s.x += n1.x + n2.x + n3.x; s.y += n1.y + n2.y + n3.y;
                s.z += n1.z + n2.z + n3.z; s.w += n1.w + n2.w + n3.w;
                g[b4 * 4 + 0] = s.x; g[b4 * 4 + 1] = s.y; g[b4 * 4 + 2] = s.z; g[b4 * 4 + 3] = s.w;
            }
            float p1[4], p2[4];
            #pragma unroll
            for (int h = 0; h < 4; h++) {
                const float4 a1a = *(const float4*)(smf + OFF_A1 + h * 36 + fb);
                const float4 a1b = *(const float4*)(smf + OFF_A1 + h * 36 + fb + 4);
                const float4 a2a = *(const float4*)(smf + OFF_A2 + h * 36 + fb);
                const float4 a2b = *(const float4*)(smf + OFF_A2 + h * 36 + fb + 4);
                p1[h] = g[0] * a1a.x + g[1] * a1a.y + g[2] * a1a.z + g[3] * a1a.w
                      + g[4] * a1b.x + g[5] * a1b.y + g[6] * a1b.z + g[7] * a1b.w;
                p2[h] = g[0] * a2a.x + g[1] * a2a.y + g[2] * a2a.z + g[3] * a2a.w
                      + g[4] * a2b.x + g[5] * a2b.y + g[6] * a2b.z + g[7] * a2b.w;
            }
            #pragma unroll
            for (int h = 0; h < 4; h++) {
                p1[h] += __shfl_xor_sync(0xFFFFFFFF, p1[h], 1);
                p1[h] += __shfl_xor_sync(0xFFFFFFFF, p1[h], 2);
                p2[h] += __shfl_xor_sync(0xFFFFFFFF, p2[h], 1);
                p2[h] += __shfl_xor_sync(0xFFFFFFFF, p2[h], 2);
            }
            if (fq == 0) {
                *(float4*)(smf + OFF_S1 + row * 4) = make_float4(p1[0], p1[1], p1[2], p1[3]);
                *(float4*)(smf + OFF_S2 + row * 4) = make_float4(p2[0], p2[1], p2[2], p2[3]);
            }
        }
        // s1s2 -> softmax only crosses the batch (warp pair)
        asm volatile("bar.sync %0, 64;" :: "r"(1 + (warp >> 1)) : "memory");

        // ---- softmax: thread -> (i = t>>2, h = t&3); attn -> [i*84 + h*20 + j] ----
        {
            const int i = t >> 2, h = t & 3;
            const int jb = i & ~15;
            const float s1 = smf[OFF_S1 + i * 4 + h];
            float sc[NN];
            float mx = -1e30f;
            #pragma unroll
            for (int j = 0; j < NN; j++) {
                float s = s1 + smf[OFF_S2 + (jb + j) * 4 + h];
                s = (s > 0.f) ? s : 0.2f * s;
                const bool valid = (amask >> j) & 1u;
                sc[j] = valid ? s : -1e30f;
                mx = (valid && s > mx) ? s : mx;
            }
            float sum = 0.f;
            #pragma unroll
            for (int j = 0; j < NN; j++) {
                const float e = (sc[j] > -1e29f) ? __expf(sc[j] - mx) : 0.f;
                sc[j] = e;
                sum += e;
            }
            const float inv = 1.f / sum;
            float* arow = smf + OFF_XA + i * 84 + h * 20;
            #pragma unroll
            for (int j4 = 0; j4 < 4; j4++)
                *(float4*)(arow + 4 * j4) = make_float4(sc[4 * j4] * inv, sc[4 * j4 + 1] * inv,
                                                        sc[4 * j4 + 2] * inv, sc[4 * j4 + 3] * inv);
        }
        __syncwarp();   // agg warp w reads attn rows 8w..8w+7 = written by this same warp

        // ---- agg: warp -> 8 i-rows, lane -> c4; j register-blocked by 4 ----
        {
            ull acc[8][2];
            #pragma unroll
            for (int r = 0; r < 8; r++) { acc[r][0] = 0; acc[r][1] = 0; }
            #pragma unroll
            for (int j4 = 0; j4 < 4; j4++) {
                ull nfv[4][2];
                #pragma unroll
                for (int jj = 0; jj < 4; jj++) {
                    const ulonglong2 v = *(const ulonglong2*)(smf + OFF_NF + (ajb + 4 * j4 + jj) * 132 + lane * 4);
                    nfv[jj][0] = v.x; nfv[jj][1] = v.y;
                }
                #pragma unroll
                for (int r = 0; r < 8; r++) {
                    const float4 af = *(const float4*)(smf + OFF_XA + (ar0 + r) * 84 + hh * 20 + 4 * j4);
                    ull aa;
                    aa = pack2(af.x, af.x);
                    fma2(acc[r][0], aa, nfv[0][0], acc[r][0]); fma2(acc[r][1], aa, nfv[0][1], acc[r][1]);
                    aa = pack2(af.y, af.y);
                    fma2(acc[r][0], aa, nfv[1][0], acc[r][0]); fma2(acc[r][1], aa, nfv[1][1], acc[r][1]);
                    aa = pack2(af.z, af.z);
                    fma2(acc[r][0], aa, nfv[2][0], acc[r][0]); fma2(acc[r][1], aa, nfv[2][1], acc[r][1]);
                    aa = pack2(af.w, af.w);
                    fma2(acc[r][0], aa, nfv[3][0], acc[r][0]); fma2(acc[r][1], aa, nfv[3][1], acc[r][1]);
                }
            }
            #pragma unroll
            for (int r = 0; r < 8; r++) {
                ulonglong2 st; st.x = acc[r][0]; st.y = acc[r][1];
                *(ulonglong2*)(out + (row0 + ar0 + r) * COLS + lane * 4) = st;
            }
        }
        __syncthreads();   // attn (OFF_XA) and NF dead before next pass overwrites
    }
}

extern "C" void kernel_launch(void* const* d_in, const int* in_sizes, int n_in,
                              void* d_out, int out_size) {
    const float* x    = (const float*)d_in[0];
    const float* W    = (const float*)d_in[1];
    const float* attv = (const float*)d_in[2];
    const float* adj  = (const float*)d_in[3];
    float* out = (float*)d_out;
    (void)in_sizes; (void)n_in; (void)out_size;

    cudaFuncSetAttribute(gat_kernel, cudaFuncAttributeMaxDynamicSharedMemorySize, SMEM_BYTES);
    gat_kernel<<<GRID, THREADS, SMEM_BYTES>>>(x, W, attv, adj, out);
}

// round 11
// speedup vs baseline: 1.2693x; 1.2693x over previous
#include <cuda_runtime.h>
#include <cstdint>

// GraphAttention: nf=x@W ; g=head-sum(nf) ; s1/s2=g.a1/a2 ; lrelu+mask+softmax(j) ; agg.
// R8 tiling (warp = 8rows-ish x 128 cols, lane->c4) + 3 blocks/SM via ROWS_PP=48.
#define NN      16
#define FINN    64
#define COLS    128
#define ROWS_PP 48          // 3 graphs per pass
#define TOTROWS 524288
#define NPASS   10923       // ceil(524288/48), last pass nv=32
#define GRID    2048
#define THREADS 256

// smem offsets (floats)
#define OFF_W   0            // [64 k][128 c]
#define OFF_NF  8192         // [48 r][132]
#define OFF_XA  14528        // x: [48 r][68] / attn: [i*68 + j*4 + h] (time-disjoint alias)
#define OFF_S1  17792        // [48][4]
#define OFF_S2  17984
#define OFF_A1  18176        // [4][36]
#define OFF_A2  18320
#define SMEM_FLOATS 18464
#define SMEM_BYTES  (SMEM_FLOATS * 4)   // 73856 B -> 3 blocks/SM

typedef unsigned long long ull;

__device__ __forceinline__ ull pack2(float lo, float hi) {
    ull o; asm("mov.b64 %0, {%1, %2};" : "=l"(o) : "f"(lo), "f"(hi)); return o;
}
__device__ __forceinline__ void fma2(ull& d, ull a, ull b, ull c) {
    asm("fma.rn.f32x2 %0, %1, %2, %3;" : "=l"(d) : "l"(a), "l"(b), "l"(c));
}

__global__ __launch_bounds__(THREADS, 3)
void gat_kernel(const float* __restrict__ x,
                const float* __restrict__ W,
                const float* __restrict__ attv,
                const float* __restrict__ adj,
                float* __restrict__ out)
{
    extern __shared__ float smf[];
    const int t = threadIdx.x;
    const int warp = t >> 5;
    const int lane = t & 31;
    const int c4 = lane;                  // col group c4*4..+3 (all 128 cols per warp)
    const int hh = c4 >> 3;

    // ---- one-time setup ----
    #pragma unroll
    for (int q = 0; q < 8; q++)
        ((float4*)(smf + OFF_W))[t + 256 * q] = ((const float4*)W)[t + 256 * q];
    {
        const int h = t >> 6, f2 = t & 63;
        const float v = attv[t];
        if (f2 < 32) smf[OFF_A1 + h * 36 + f2] = v;
        else         smf[OFF_A2 + h * 36 + (f2 - 32)] = v;
    }
    unsigned amask = 0;
    {
        const int i = (t >> 2) & 15;
        #pragma unroll
        for (int j = 0; j < NN; j++)
            if (adj[i * NN + j] != 0.f) amask |= (1u << j);
    }
    __syncthreads();

    for (int tp = blockIdx.x; tp < NPASS; tp += GRID) {
        const size_t row0 = (size_t)tp * ROWS_PP;
        const int nv = (row0 + ROWS_PP <= TOTROWS) ? ROWS_PP : (int)(TOTROWS - row0);

        // ---- stage x (nv x 64) -> pitch-68 ----
        {
            const float4* gx = (const float4*)(x + row0 * FINN);
            #pragma unroll
            for (int q = 0; q < 3; q++) {
                const int idx = t + 256 * q;
                if ((idx >> 4) < nv) {
                    const float4 v = gx[idx];
                    *(float4*)(smf + OFF_XA + (idx >> 4) * 68 + 4 * (idx & 15)) = v;
                }
            }
        }
        __syncthreads();

        // ---- GEMM: warp -> rows 6w..6w+5, lane -> 4 cols (128 cols/warp) ----
        {
            const float* xrow = smf + OFF_XA + (6 * warp) * 68;
            const float* wcol = smf + OFF_W + c4 * 4;
            ull acc[6][2];
            #pragma unroll
            for (int r = 0; r < 6; r++) { acc[r][0] = 0; acc[r][1] = 0; }
            #pragma unroll
            for (int k4 = 0; k4 < 16; k4++) {
                const ulonglong2 w0 = *(const ulonglong2*)(wcol + (k4 * 4 + 0) * COLS);
                const ulonglong2 w1 = *(const ulonglong2*)(wcol + (k4 * 4 + 1) * COLS);
                const ulonglong2 w2 = *(const ulonglong2*)(wcol + (k4 * 4 + 2) * COLS);
                const ulonglong2 w3 = *(const ulonglong2*)(wcol + (k4 * 4 + 3) * COLS);
                #pragma unroll
                for (int r = 0; r < 6; r++) {
                    const float4 xv = *(const float4*)(xrow + r * 68 + k4 * 4);
                    ull xx;
                    xx = pack2(xv.x, xv.x);
                    fma2(acc[r][0], xx, w0.x, acc[r][0]); fma2(acc[r][1], xx, w0.y, acc[r][1]);
                    xx = pack2(xv.y, xv.y);
                    fma2(acc[r][0], xx, w1.x, acc[r][0]); fma2(acc[r][1], xx, w1.y, acc[r][1]);
                    xx = pack2(xv.z, xv.z);
                    fma2(acc[r][0], xx, w2.x, acc[r][0]); fma2(acc[r][1], xx, w2.y, acc[r][1]);
                    xx = pack2(xv.w, xv.w);
                    fma2(acc[r][0], xx, w3.x, acc[r][0]); fma2(acc[r][1], xx, w3.y, acc[r][1]);
                }
            }
            #pragma unroll
            for (int r = 0; r < 6; r++) {
                if (6 * warp + r < nv) {
                    ulonglong2 st; st.x = acc[r][0]; st.y = acc[r][1];
                    *(ulonglong2*)(smf + OFF_NF + (6 * warp + r) * 132 + c4 * 4) = st;
                }
            }
        }
        __syncthreads();

        if (warp < 6) {
            const int row = t >> 2, fq = t & 3;      // row 0..47
            // ---- s1/s2: thread -> (row, fq -> 8 f's); shfl-reduce over fq ----
            if (row < nv) {
                const int fb = fq * 8;
                const float* nfr = smf + OFF_NF + row * 132 + fb;
                float g[8];
                #pragma unroll
                for (int b4 = 0; b4 < 2; b4++) {
                    float4 s = *(const float4*)(nfr + b4 * 4);
                    const float4 n1 = *(const float4*)(nfr + 32 + b4 * 4);
                    const float4 n2 = *(const float4*)(nfr + 64 + b4 * 4);
                    const float4 n3 = *(const float4*)(nfr + 96 + b4 * 4);
                    s.x += n1.x + n2.x + n3.x; s.y += n1.y + n2.y + n3.y;
                    s.z += n1.z + n2.z + n3.z; s.w += n1.w + n2.w + n3.w;
                    g[b4 * 4 + 0] = s.x; g[b4 * 4 + 1] = s.y; g[b4 * 4 + 2] = s.z; g[b4 * 4 + 3] = s.w;
                }
                float p1[4], p2[4];
                #pragma unroll
                for (int h = 0; h < 4; h++) {
                    const float4 a1a = *(const float4*)(smf + OFF_A1 + h * 36 + fb);
                    const float4 a1b = *(const float4*)(smf + OFF_A1 + h * 36 + fb + 4);
                    const float4 a2a = *(const float4*)(smf + OFF_A2 + h * 36 + fb);
                    const float4 a2b = *(const float4*)(smf + OFF_A2 + h * 36 + fb + 4);
                    p1[h] = g[0] * a1a.x + g[1] * a1a.y + g[2] * a1a.z + g[3] * a1a.w
                          + g[4] * a1b.x + g[5] * a1b.y + g[6] * a1b.z + g[7] * a1b.w;
                    p2[h] = g[0] * a2a.x + g[1] * a2a.y + g[2] * a2a.z + g[3] * a2a.w
                          + g[4] * a2b.x + g[5] * a2b.y + g[6] * a2b.z + g[7] * a2b.w;
                }
                #pragma unroll
                for (int h = 0; h < 4; h++) {
                    p1[h] += __shfl_xor_sync(0xFFFFFFFF, p1[h], 1);
                    p1[h] += __shfl_xor_sync(0xFFFFFFFF, p1[h], 2);
                    p2[h] += __shfl_xor_sync(0xFFFFFFFF, p2[h], 1);
                    p2[h] += __shfl_xor_sync(0xFFFFFFFF, p2[h], 2);
                }
                if (fq == 0) {
                    *(float4*)(smf + OFF_S1 + row * 4) = make_float4(p1[0], p1[1], p1[2], p1[3]);
                    *(float4*)(smf + OFF_S2 + row * 4) = make_float4(p2[0], p2[1], p2[2], p2[3]);
                }
            }
            // graph = 16 rows = 64 threads = this warp pair
            asm volatile("bar.sync %0, 64;" :: "r"(1 + (warp >> 1)) : "memory");

            // ---- softmax: thread -> (i = row, h = fq); attn -> [i*68 + j*4 + h] ----
            if (row < nv) {
                const int i = row, h = fq;
                const int jb = i & ~15;
                const float s1 = smf[OFF_S1 + i * 4 + h];
                float sc[NN];
                float mx = -1e30f;
                #pragma unroll
                for (int j = 0; j < NN; j++) {
                    float s = s1 + smf[OFF_S2 + (jb + j) * 4 + h];
                    s = (s > 0.f) ? s : 0.2f * s;
                    const bool valid = (amask >> j) & 1u;
                    sc[j] = valid ? s : -1e30f;
                    mx = (valid && s > mx) ? s : mx;
                }
                float sum = 0.f;
                #pragma unroll
                for (int j = 0; j < NN; j++) {
                    const float e = (sc[j] > -1e29f) ? __expf(sc[j] - mx) : 0.f;
                    sc[j] = e;
                    sum += e;
                }
                const float inv = 1.f / sum;
                #pragma unroll
                for (int j = 0; j < NN; j++)
                    smf[OFF_XA + i * 68 + j * 4 + h] = sc[j] * inv;
            }
            asm volatile("bar.sync %0, 64;" :: "r"(1 + (warp >> 1)) : "memory");

            // ---- agg: warp pair -> one graph; warp -> 8 i-rows, lane -> c4 ----
            {
                const int g  = warp >> 1;
                const int jb = g * 16;
                if (jb < nv) {
                    const int ar0 = jb + (warp & 1) * 8;
                    ull acc[8][2];
                    #pragma unroll
                    for (int r = 0; r < 8; r++) { acc[r][0] = 0; acc[r][1] = 0; }
                    #pragma unroll
                    for (int j4 = 0; j4 < 4; j4++) {
                        ull nfv[4][2];
                        #pragma unroll
                        for (int jj = 0; jj < 4; jj++) {
                            const ulonglong2 v = *(const ulonglong2*)(smf + OFF_NF + (jb + 4 * j4 + jj) * 132 + c4 * 4);
                            nfv[jj][0] = v.x; nfv[jj][1] = v.y;
                        }
                        #pragma unroll
                        for (int r = 0; r < 8; r++) {
                            const float* ap = smf + OFF_XA + (ar0 + r) * 68 + hh;
                            ull aa;
                            float a;
                            a = ap[(4 * j4 + 0) * 4]; aa = pack2(a, a);
                            fma2(acc[r][0], aa, nfv[0][0], acc[r][0]); fma2(acc[r][1], aa, nfv[0][1], acc[r][1]);
                            a = ap[(4 * j4 + 1) * 4]; aa = pack2(a, a);
                            fma2(acc[r][0], aa, nfv[1][0], acc[r][0]); fma2(acc[r][1], aa, nfv[1][1], acc[r][1]);
                            a = ap[(4 * j4 + 2) * 4]; aa = pack2(a, a);
                            fma2(acc[r][0], aa, nfv[2][0], acc[r][0]); fma2(acc[r][1], aa, nfv[2][1], acc[r][1]);
                            a = ap[(4 * j4 + 3) * 4]; aa = pack2(a, a);
                            fma2(acc[r][0], aa, nfv[3][0], acc[r][0]); fma2(acc[r][1], aa, nfv[3][1], acc[r][1]);
                        }
                    }
                    #pragma unroll
                    for (int r = 0; r < 8; r++) {
                        ulonglong2 st; st.x = acc[r][0]; st.y = acc[r][1];
                        *(ulonglong2*)(out + (row0 + ar0 + r) * COLS + c4 * 4) = st;
                    }
                }
            }
        }
        __syncthreads();   // attn/x (OFF_XA) and NF dead before next pass
    }
}

extern "C" void kernel_launch(void* const* d_in, const int* in_sizes, int n_in,
                              void* d_out, int out_size) {
    const float* x    = (const float*)d_in[0];
    const float* W    = (const float*)d_in[1];
    const float* attv = (const float*)d_in[2];
    const float* adj  = (const float*)d_in[3];
    float* out = (float*)d_out;
    (void)in_sizes; (void)n_in; (void)out_size;

    cudaFuncSetAttribute(gat_kernel, cudaFuncAttributeMaxDynamicSharedMemorySize, SMEM_BYTES);
    gat_kernel<<<GRID, THREADS, SMEM_BYTES>>>(x, W, attv, adj, out);
}